// round 13
// baseline (speedup 1.0000x reference)
#include <cuda_runtime.h>
#include <cstdint>

#define TSTEPS 256
#define HSZ 50
#define ISZ 7
#define EPB 32
#define NTH 256
#define NBLK 128
#define MW 7           // MMA warps; warp w owns cells w*8..w*8+7 (two m16 tiles)
#define K0C 8          // layer0 K chunks (cols 0..63: 50 h0 + 7 x + pad)
#define K1C 14         // layer1 K chunks (cols 0..111: 50 h0 + pad + h1 ping/pong)
#define SW 116         // W1 row stride (224 rows)
#define S0 68          // T0 row stride (32 rows, double buffered)
#define S1 172         // T1 row stride (32 rows; h0 @0-49, h1 @56-105 / 112-161)

// smem float offsets
#define OFF_W1 0                   // [224][116] = 25984
#define OFF_T0 25984               // [2][32][68] = 4352
#define OFF_T1 30336               // [32][172]   = 5504
#define SMEMF  35840               // 143360 bytes

__device__ __forceinline__ float sigm(float v) {
    return __fdividef(1.f, 1.f + __expf(-v));
}
__device__ __forceinline__ float tanh_f(float v) {
    return __fdividef(2.f, 1.f + __expf(-2.f * v)) - 1.f;
}
__device__ __forceinline__ uint32_t tf32u(float f) {
    uint32_t u; asm("cvt.rna.tf32.f32 %0, %1;" : "=r"(u) : "f"(f)); return u;
}
__device__ __forceinline__ float tf32f(float f) {
    return __uint_as_float(tf32u(f));
}
__device__ __forceinline__ void mma_tf32(float d[4], const uint32_t a[4],
                                         uint32_t b0, uint32_t b1) {
    asm volatile(
        "mma.sync.aligned.m16n8k8.row.col.f32.tf32.tf32.f32 "
        "{%0,%1,%2,%3}, {%4,%5,%6,%7}, {%8,%9}, {%0,%1,%2,%3};"
        : "+f"(d[0]), "+f"(d[1]), "+f"(d[2]), "+f"(d[3])
        : "r"(a[0]), "r"(a[1]), "r"(a[2]), "r"(a[3]), "r"(b0), "r"(b1));
}

// layer0 weight element for (cell j, gate gi, col c over [h0(50) | x(7) | 0])
__device__ __forceinline__ float w0v(const float* __restrict__ wih0,
                                     const float* __restrict__ whh0,
                                     int j, int gi, int c) {
    if (j >= HSZ) return 0.f;
    if (c < 50) return whh0[(gi * HSZ + j) * HSZ + c];
    if (c < 57) return wih0[(gi * HSZ + j) * ISZ + (c - 50)];
    return 0.f;
}

__global__ __launch_bounds__(NTH, 1)
void lstm2_tc_v8(const float* __restrict__ x,
                 const float* __restrict__ w_ih0, const float* __restrict__ w_hh0,
                 const float* __restrict__ b_ih0, const float* __restrict__ b_hh0,
                 const float* __restrict__ w_ih1, const float* __restrict__ w_hh1,
                 const float* __restrict__ b_ih1, const float* __restrict__ b_hh1,
                 const float* __restrict__ w_fc,  const float* __restrict__ b_fc,
                 float* __restrict__ out)
{
    extern __shared__ float sm[];
    const int tid  = threadIdx.x;
    const int blk  = blockIdx.x;
    const int wid  = tid >> 5;
    const int lane = tid & 31;
    const int gid  = lane >> 2;     // 0..7
    const int t4   = lane & 3;      // 0..3
    const int j    = wid * 8 + gid; // this lane's cell (valid < 50)
    const bool mma_w = (wid < MW);

    // ---- stage layer1 weights, permuted rows: r = w*32 + tile*16 + half*8 + g
    //      cell = w*8+g, gate = tile*2+half; cols: ih1 @0-49, pad 50-55, hh1 @56-105 ----
    for (int i = tid; i < 224 * SW; i += NTH) {
        const int r = i / SW, c = i % SW;
        const int w = r >> 5, rem = r & 31;
        const int tile = rem >> 4, half = (rem >> 3) & 1, g = rem & 7;
        const int cell = w * 8 + g, gate = tile * 2 + half;
        float v = 0.f;
        if (cell < HSZ) {
            if (c < 50)                 v = w_ih1[(gate * HSZ + cell) * HSZ + c];
            else if (c >= 56 && c < 106) v = w_hh1[(gate * HSZ + cell) * HSZ + (c - 56)];
        }
        sm[OFF_W1 + i] = tf32f(v);
    }
    // zero operand buffers
    for (int i = tid; i < 2 * 32 * S0; i += NTH) sm[OFF_T0 + i] = 0.f;
    for (int i = tid; i < 32 * S1; i += NTH) sm[OFF_T1 + i] = 0.f;
    __syncthreads();
    // x(t=0) into T0 buf0 cols 50..56
    if (tid < 224) {
        const int e = tid / 7, kx = tid % 7;
        sm[OFF_T0 + e * S0 + 50 + kx] =
            tf32f(x[(size_t)(blk * EPB + e) * (TSTEPS * ISZ) + kx]);
    }

    // ---- layer0 A fragments in registers: tileA rows = (i,f), tileB rows = (g,o) of cell j ----
    uint32_t wa0A[K0C][4], wa0B[K0C][4];
    if (mma_w) {
        #pragma unroll
        for (int kc = 0; kc < K0C; kc++) {
            const int c0 = kc * 8 + t4, c1 = c0 + 4;
            wa0A[kc][0] = tf32u(w0v(w_ih0, w_hh0, j, 0, c0));
            wa0A[kc][1] = tf32u(w0v(w_ih0, w_hh0, j, 1, c0));
            wa0A[kc][2] = tf32u(w0v(w_ih0, w_hh0, j, 0, c1));
            wa0A[kc][3] = tf32u(w0v(w_ih0, w_hh0, j, 1, c1));
            wa0B[kc][0] = tf32u(w0v(w_ih0, w_hh0, j, 2, c0));
            wa0B[kc][1] = tf32u(w0v(w_ih0, w_hh0, j, 3, c0));
            wa0B[kc][2] = tf32u(w0v(w_ih0, w_hh0, j, 2, c1));
            wa0B[kc][3] = tf32u(w0v(w_ih0, w_hh0, j, 3, c1));
        }
    }
    // per-lane biases
    float bi0 = 0.f, bf0 = 0.f, bg0 = 0.f, bo0 = 0.f;
    float bi1 = 0.f, bf1 = 0.f, bg1 = 0.f, bo1 = 0.f;
    if (mma_w && j < HSZ) {
        bi0 = b_ih0[0 * HSZ + j] + b_hh0[0 * HSZ + j];
        bf0 = b_ih0[1 * HSZ + j] + b_hh0[1 * HSZ + j];
        bg0 = b_ih0[2 * HSZ + j] + b_hh0[2 * HSZ + j];
        bo0 = b_ih0[3 * HSZ + j] + b_hh0[3 * HSZ + j];
        bi1 = b_ih1[0 * HSZ + j] + b_hh1[0 * HSZ + j];
        bf1 = b_ih1[1 * HSZ + j] + b_hh1[1 * HSZ + j];
        bg1 = b_ih1[2 * HSZ + j] + b_hh1[2 * HSZ + j];
        bo1 = b_ih1[3 * HSZ + j] + b_hh1[3 * HSZ + j];
    }

    const float* xp = x;
    if (tid < 224)
        xp = x + (size_t)(blk * EPB + tid / 7) * (TSTEPS * ISZ) + (tid % 7);

    float c0s[8] = {0.f,0.f,0.f,0.f,0.f,0.f,0.f,0.f};
    float c1s[8] = {0.f,0.f,0.f,0.f,0.f,0.f,0.f,0.f};
    const bool jok = (j < HSZ);

    __syncthreads();

    int buf = 0;
    for (int t = 0; t < TSTEPS; t++) {
        float xv = 0.f;
        if (tid < 224 && t + 1 < TSTEPS) xv = xp[(t + 1) * ISZ];

        const int RB = (t & 1) ? 112 : 56;   // h1 read base this step
        const int WB = (t & 1) ? 56 : 112;   // h1 write base this step
        const float* T0r = sm + OFF_T0 + buf * (32 * S0);
        float* T0w = sm + OFF_T0 + (buf ^ 1) * (32 * S0);

        // ======== P1: layer0 MMA + in-lane activation ========
        if (mma_w) {
            float accA[4][4], accB[4][4];
            #pragma unroll
            for (int n = 0; n < 4; n++) {
                accA[n][0] = bi0; accA[n][1] = bi0; accA[n][2] = bf0; accA[n][3] = bf0;
                accB[n][0] = bg0; accB[n][1] = bg0; accB[n][2] = bo0; accB[n][3] = bo0;
            }
            #pragma unroll
            for (int kc = 0; kc < K0C; kc++) {
                #pragma unroll
                for (int n = 0; n < 4; n++) {
                    const float* bp = T0r + (n * 8 + gid) * S0 + kc * 8 + t4;
                    const uint32_t b0 = __float_as_uint(bp[0]);
                    const uint32_t b1 = __float_as_uint(bp[4]);
                    mma_tf32(accA[n], wa0A[kc], b0, b1);
                    mma_tf32(accB[n], wa0B[kc], b0, b1);
                }
            }
            #pragma unroll
            for (int n = 0; n < 4; n++) {
                #pragma unroll
                for (int p = 0; p < 2; p++) {
                    const int e = n * 8 + t4 * 2 + p;
                    const int idx = n * 2 + p;
                    const float iv = accA[n][p], fv = accA[n][2 + p];
                    const float gv = accB[n][p], ov = accB[n][2 + p];
                    c0s[idx] = sigm(fv) * c0s[idx] + sigm(iv) * tanh_f(gv);
                    const float h0 = sigm(ov) * tanh_f(c0s[idx]);
                    if (jok) {
                        const float ht = tf32f(h0);
                        T0w[e * S0 + j] = ht;             // layer0 h for t+1
                        sm[OFF_T1 + e * S1 + j] = ht;     // layer1 input (cols 0-49)
                    }
                }
            }
        }
        __syncthreads();   // barA: h0 + T1 inputs visible

        // x_{t+1} into the other T0 buffer (no reader of T0 in P2)
        if (tid < 224) T0w[(tid / 7) * S0 + 50 + tid % 7] = tf32f(xv);

        // ======== P2: layer1 MMA + in-lane activation ========
        if (mma_w) {
            float accA[4][4], accB[4][4];
            #pragma unroll
            for (int n = 0; n < 4; n++) {
                accA[n][0] = bi1; accA[n][1] = bi1; accA[n][2] = bf1; accA[n][3] = bf1;
                accB[n][0] = bg1; accB[n][1] = bg1; accB[n][2] = bo1; accB[n][3] = bo1;
            }
            const int rA = wid * 32 + gid;        // tileA rows (i,f)
            const int rB = wid * 32 + 16 + gid;   // tileB rows (g,o)
            #pragma unroll
            for (int kc = 0; kc < K1C; kc++) {
                const int acol = kc * 8 + t4;
                const int bcol = (kc < 7) ? (kc * 8 + t4) : (RB + (kc - 7) * 8 + t4);
                uint32_t aA[4], aB[4];
                {
                    const float* ap = sm + OFF_W1 + rA * SW + acol;
                    aA[0] = __float_as_uint(ap[0]);
                    aA[1] = __float_as_uint(ap[8 * SW]);
                    aA[2] = __float_as_uint(ap[4]);
                    aA[3] = __float_as_uint(ap[8 * SW + 4]);
                }
                {
                    const float* ap = sm + OFF_W1 + rB * SW + acol;
                    aB[0] = __float_as_uint(ap[0]);
                    aB[1] = __float_as_uint(ap[8 * SW]);
                    aB[2] = __float_as_uint(ap[4]);
                    aB[3] = __float_as_uint(ap[8 * SW + 4]);
                }
                #pragma unroll
                for (int n = 0; n < 4; n++) {
                    const float* bp = sm + OFF_T1 + (n * 8 + gid) * S1 + bcol;
                    const uint32_t b0 = __float_as_uint(bp[0]);
                    const uint32_t b1 = __float_as_uint(bp[4]);
                    mma_tf32(accA[n], aA, b0, b1);
                    mma_tf32(accB[n], aB, b0, b1);
                }
            }
            #pragma unroll
            for (int n = 0; n < 4; n++) {
                #pragma unroll
                for (int p = 0; p < 2; p++) {
                    const int e = n * 8 + t4 * 2 + p;
                    const int idx = n * 2 + p;
                    const float iv = accA[n][p], fv = accA[n][2 + p];
                    const float gv = accB[n][p], ov = accB[n][2 + p];
                    c1s[idx] = sigm(fv) * c1s[idx] + sigm(iv) * tanh_f(gv);
                    const float h1 = sigm(ov) * tanh_f(c1s[idx]);
                    if (jok) sm[OFF_T1 + e * S1 + WB + j] = tf32f(h1);
                }
            }
        }
        __syncthreads();   // barB: h1(WB) + x visible for next step
        buf ^= 1;
    }

    // ---- FC head: final h1 at cols 56..105 (t=255 wrote WB=56) ----
    if (tid < 224) {
        const int i = tid % 7, e = tid / 7;
        float s = b_fc[i];
        #pragma unroll 10
        for (int k = 0; k < HSZ; k++)
            s = fmaf(w_fc[i * HSZ + k], sm[OFF_T1 + e * S1 + 56 + k], s);
        out[(size_t)(blk * EPB + e) * ISZ + i] = s;
    }
}

extern "C" void kernel_launch(void* const* d_in, const int* in_sizes, int n_in,
                              void* d_out, int out_size)
{
    const float* x     = (const float*)d_in[0];
    const float* w_ih0 = (const float*)d_in[1];
    const float* w_hh0 = (const float*)d_in[2];
    const float* b_ih0 = (const float*)d_in[3];
    const float* b_hh0 = (const float*)d_in[4];
    const float* w_ih1 = (const float*)d_in[5];
    const float* w_hh1 = (const float*)d_in[6];
    const float* b_ih1 = (const float*)d_in[7];
    const float* b_hh1 = (const float*)d_in[8];
    const float* w_fc  = (const float*)d_in[9];
    const float* b_fc  = (const float*)d_in[10];
    float* out = (float*)d_out;

    const size_t smem_bytes = SMEMF * sizeof(float);
    cudaFuncSetAttribute(lstm2_tc_v8,
                         cudaFuncAttributeMaxDynamicSharedMemorySize,
                         (int)smem_bytes);

    lstm2_tc_v8<<<NBLK, NTH, smem_bytes>>>(
        x, w_ih0, w_hh0, b_ih0, b_hh0,
        w_ih1, w_hh1, b_ih1, b_hh1,
        w_fc, b_fc, out);
}